// round 9
// baseline (speedup 1.0000x reference)
#include <cuda_runtime.h>
#include <cuda_fp16.h>
#include <math.h>
#include <stdint.h>

#define Bsz   64
#define Ssz   2048
#define ENCd  512
#define ATTNd 256

#define TILE_S 128
#define KC     64                    // k per chunk
#define NCHUNK (ENCd / KC)           // 8
#define ABYTES (TILE_S * 128)        // 16384 (128 rows x 128B fp16)
#define BBYTES (ATTNd * 128)         // 32768
#define NTHR   512

// smem offsets
#define SM_DP   0
#define SM_V    1024
#define SM_RED  2048                 // 128*8 floats = 4KB
#define SM_A0   8192
#define SM_B0   (SM_A0 + 2 * ABYTES)          // 40960
#define SM_TOTAL (SM_B0 + 2 * BBYTES)         // 106496

#define CSPLIT 16

__device__ float  g_dec_proj[Bsz * ATTNd];
__device__ float  g_scores[Bsz * Ssz];
__device__ float  g_ctx_part[CSPLIT * Bsz * ENCd];
__device__ __half g_Bh[ENCd * ATTNd];          // pre-swizzled fp16 W_enc^T image
__device__ __half g_ench[(size_t)Bsz * Ssz * ENCd];  // fp16 enc image (written by scores)

// ---------------------------------------------------------------------------
// helpers
// ---------------------------------------------------------------------------
__device__ __forceinline__ float tanh_fast(float x) {
    float y;
    asm("tanh.approx.f32 %0, %1;" : "=f"(y) : "f"(x));
    return y;
}
__device__ __forceinline__ uint32_t smem_u32(const void* p) {
    uint32_t a;
    asm("{ .reg .u64 t; cvta.to.shared.u64 t, %1; cvt.u32.u64 %0, t; }" : "=r"(a) : "l"(p));
    return a;
}
__device__ __forceinline__ uint32_t pack_h2(float lo, float hi) {
    uint32_t r;
    asm("cvt.rn.f16x2.f32 %0, %1, %2;" : "=r"(r) : "f"(hi), "f"(lo));
    return r;
}
__device__ __forceinline__ void cp_async16(uint32_t dst, const void* src) {
    asm volatile("cp.async.cg.shared.global [%0], [%1], 16;" :: "r"(dst), "l"(src));
}
#define CP_COMMIT() asm volatile("cp.async.commit_group;" ::: "memory")

__device__ __forceinline__ void ldsm_x4(uint32_t* r, uint32_t addr) {
    asm volatile("ldmatrix.sync.aligned.m8n8.x4.shared.b16 {%0,%1,%2,%3}, [%4];"
                 : "=r"(r[0]), "=r"(r[1]), "=r"(r[2]), "=r"(r[3]) : "r"(addr));
}
__device__ __forceinline__ void mma_f16(float c[4], const uint32_t a[4],
                                        uint32_t b0, uint32_t b1) {
    asm volatile(
        "mma.sync.aligned.m16n8k16.row.col.f32.f16.f16.f32 "
        "{%0,%1,%2,%3}, {%4,%5,%6,%7}, {%8,%9}, {%0,%1,%2,%3};"
        : "+f"(c[0]), "+f"(c[1]), "+f"(c[2]), "+f"(c[3])
        : "r"(a[0]), "r"(a[1]), "r"(a[2]), "r"(a[3]), "r"(b0), "r"(b1));
}

// ---------------------------------------------------------------------------
// Kernel P: pre-swizzled fp16 image of B (W_enc^T), 128B rows of 64 k-halves,
// SW128 baked: 16B-chunk j -> j ^ (n&7), per k-chunk c.
// ---------------------------------------------------------------------------
__global__ __launch_bounds__(256) void prep_bh_kernel(const float* __restrict__ W_enc) {
    int idx = blockIdx.x * 256 + threadIdx.x;   // k-major
    int k = idx >> 8, n = idx & 255;
    int c = k >> 6, j = (k >> 3) & 7, w = k & 7;
    int phys = j ^ (n & 7);
    g_Bh[(((size_t)c * 256 + n) * 8 + phys) * 8 + w] = __float2half_rn(W_enc[idx]);
}

// ---------------------------------------------------------------------------
// Kernel 0: dec_proj (4 independent accumulator chains)
// ---------------------------------------------------------------------------
__global__ __launch_bounds__(256) void dec_proj_kernel(const float* __restrict__ dec_state,
                                                       const float* __restrict__ W_dec) {
    int b = blockIdx.x;
    int n = threadIdx.x;
    __shared__ float ds[ENCd];
    for (int i = threadIdx.x; i < ENCd; i += 256) ds[i] = dec_state[b * ENCd + i];
    __syncthreads();
    float a0 = 0.f, a1 = 0.f, a2 = 0.f, a3 = 0.f;
#pragma unroll 4
    for (int d = 0; d < ENCd; d += 4) {
        a0 += ds[d]     * W_dec[(d)     * ATTNd + n];
        a1 += ds[d + 1] * W_dec[(d + 1) * ATTNd + n];
        a2 += ds[d + 2] * W_dec[(d + 2) * ATTNd + n];
        a3 += ds[d + 3] * W_dec[(d + 3) * ATTNd + n];
    }
    g_dec_proj[b * ATTNd + n] = (a0 + a1) + (a2 + a3);
}

// ---------------------------------------------------------------------------
// Kernel 1: scores via fp16 mma.sync (fp32 acc), 512 threads.
// Also writes the converted fp16 A-tiles back to g_ench (each enc element is
// staged by exactly one CTA exactly once).
// ---------------------------------------------------------------------------
__global__ __launch_bounds__(NTHR) void scores_kernel(const float* __restrict__ enc,
                                                      const float* __restrict__ v) {
    extern __shared__ __align__(1024) char sm[];
    const uint32_t smb = smem_u32(sm);
    const int tid = threadIdx.x, wid = tid >> 5, lane = tid & 31;
    const int b = blockIdx.y, s0 = blockIdx.x * TILE_S;
    const int gid = lane >> 2, tig = lane & 3;
    const int warp_m = wid >> 3, warp_n = wid & 7;
    const int m_base = warp_m * 64, n_base = warp_n * 32;

    float* dp_sm = (float*)(sm + SM_DP);
    float* v_sm  = (float*)(sm + SM_V);
    float* red   = (float*)(sm + SM_RED);

    if (tid < ATTNd) {
        dp_sm[tid] = g_dec_proj[b * ATTNd + tid];
        v_sm[tid]  = v[tid];
    }

    float acc[4][4][4];
#pragma unroll
    for (int mt = 0; mt < 4; mt++)
#pragma unroll
        for (int nt = 0; nt < 4; nt++)
#pragma unroll
            for (int i = 0; i < 4; i++) acc[mt][nt][i] = 0.f;

    const float* encb = enc + ((size_t)b * Ssz + s0) * ENCd;

    // ldmatrix address invariants
    const int lane15 = lane & 15;
    const int l16 = lane >> 4;                 // A k-half select
    int a_rowrel[4], a_rx[4];
#pragma unroll
    for (int mt = 0; mt < 4; mt++) {
        int r = m_base + mt * 16 + lane15;
        a_rowrel[mt] = r * 128;
        a_rx[mt] = r & 7;
    }
    const int b_lrow = (lane & 7) + ((lane >> 4) & 1) * 8;
    const int b_co = (lane >> 3) & 1;          // B k-half select
    int b_rowrel[2], b_rx[2];
#pragma unroll
    for (int pr = 0; pr < 2; pr++) {
        int r = n_base + pr * 16 + b_lrow;
        b_rowrel[pr] = r * 128;
        b_rx[pr] = r & 7;
    }

    // A staging: thread -> row = tid>>2 (0..127), quarter aq = tid&3 (16 k's)
    const int arow = tid >> 2, aq = tid & 3, arx = arow & 7;
    const float* asrc = encb + (size_t)arow * ENCd + aq * 16;
    char* const abase = sm + SM_A0 + arow * 128;
    // fp16 write-back destination for this thread's 16 halves (per chunk offset c*KC)
    __half* const hdst = g_ench + ((size_t)b * Ssz + s0 + arow) * ENCd + aq * 16;

    float4 pa[4];
#define LDG_A(c_) do {                                                         \
        const float* p_ = asrc + (c_) * KC;                                    \
        _Pragma("unroll")                                                      \
        for (int q_ = 0; q_ < 4; q_++)                                         \
            pa[q_] = *reinterpret_cast<const float4*>(p_ + q_ * 4);            \
    } while (0)

#define STS_A(st_, c_) do {                                                    \
        char* ab_ = abase + (st_) * ABYTES;                                    \
        uint4 u0_, u1_;                                                        \
        u0_.x = pack_h2(pa[0].x, pa[0].y);                                     \
        u0_.y = pack_h2(pa[0].z, pa[0].w);                                     \
        u0_.z = pack_h2(pa[1].x, pa[1].y);                                     \
        u0_.w = pack_h2(pa[1].z, pa[1].w);                                     \
        u1_.x = pack_h2(pa[2].x, pa[2].y);                                     \
        u1_.y = pack_h2(pa[2].z, pa[2].w);                                     \
        u1_.z = pack_h2(pa[3].x, pa[3].y);                                     \
        u1_.w = pack_h2(pa[3].z, pa[3].w);                                     \
        *reinterpret_cast<uint4*>(ab_ + (((aq * 2) ^ arx) << 4)) = u0_;        \
        *reinterpret_cast<uint4*>(ab_ + (((aq * 2 + 1) ^ arx) << 4)) = u1_;    \
        uint4* g_ = reinterpret_cast<uint4*>(hdst + (c_) * KC);                \
        g_[0] = u0_;                                                           \
        g_[1] = u1_;                                                           \
    } while (0)

#define CPA_B(c_, st_) do {                                                    \
        uint32_t bd_ = smb + SM_B0 + (st_) * BBYTES;                           \
        const char* bs_ = (const char*)g_Bh + (size_t)(c_) * BBYTES;           \
        _Pragma("unroll")                                                      \
        for (int i_ = 0; i_ < 4; i_++) {                                       \
            int q_ = tid + i_ * NTHR;                                          \
            cp_async16(bd_ + q_ * 16, bs_ + q_ * 16);                          \
        }                                                                      \
        CP_COMMIT();                                                           \
    } while (0)

    // prologue
    LDG_A(0);
    CPA_B(0, 0);

    for (int c = 0; c < NCHUNK; c++) {
        const int st = c & 1;
        STS_A(st, c);
        asm volatile("cp.async.wait_group 0;" ::: "memory");
        __syncthreads();

        if (c + 1 < NCHUNK) {
            CPA_B(c + 1, st ^ 1);
            LDG_A(c + 1);
        }

        const uint32_t Au = smb + SM_A0 + st * ABYTES;
        const uint32_t Bu = smb + SM_B0 + st * BBYTES;
#pragma unroll
        for (int kk = 0; kk < 4; kk++) {
            uint32_t af[4][4], bf[2][4];
#pragma unroll
            for (int mt = 0; mt < 4; mt++)
                ldsm_x4(af[mt], Au + a_rowrel[mt] + (((2 * kk + l16) ^ a_rx[mt]) << 4));
#pragma unroll
            for (int pr = 0; pr < 2; pr++)
                ldsm_x4(bf[pr], Bu + b_rowrel[pr] + (((2 * kk + b_co) ^ b_rx[pr]) << 4));
#pragma unroll
            for (int mt = 0; mt < 4; mt++)
#pragma unroll
                for (int nt = 0; nt < 4; nt++) {
                    int pr = nt >> 1, bi = (nt & 1) * 2;
                    mma_f16(acc[mt][nt], af[mt], bf[pr][bi], bf[pr][bi + 1]);
                }
        }
    }
#undef LDG_A
#undef STS_A
#undef CPA_B

    // Epilogue: rowsum over this warp's n32 of tanh(D + dec_proj) * v
    float rowsum[8];
#pragma unroll
    for (int i = 0; i < 8; i++) rowsum[i] = 0.f;
#pragma unroll
    for (int mt = 0; mt < 4; mt++)
#pragma unroll
        for (int nt = 0; nt < 4; nt++) {
            int c0 = n_base + nt * 8 + tig * 2;
#pragma unroll
            for (int i = 0; i < 2; i++)
#pragma unroll
                for (int j = 0; j < 2; j++) {
                    int col = c0 + j;
                    rowsum[mt * 2 + i] +=
                        tanh_fast(acc[mt][nt][i * 2 + j] + dp_sm[col]) * v_sm[col];
                }
        }
#pragma unroll
    for (int i = 0; i < 8; i++) {
        rowsum[i] += __shfl_xor_sync(0xffffffff, rowsum[i], 1);
        rowsum[i] += __shfl_xor_sync(0xffffffff, rowsum[i], 2);
    }
    __syncthreads();
    if (tig == 0) {
#pragma unroll
        for (int mt = 0; mt < 4; mt++)
#pragma unroll
            for (int i = 0; i < 2; i++) {
                int row = m_base + mt * 16 + gid + 8 * i;
                red[row * 8 + warp_n] = rowsum[mt * 2 + i];
            }
    }
    __syncthreads();
    if (tid < TILE_S) {
        float4 r0 = *reinterpret_cast<float4*>(&red[tid * 8]);
        float4 r1 = *reinterpret_cast<float4*>(&red[tid * 8 + 4]);
        g_scores[b * Ssz + s0 + tid] =
            ((r0.x + r0.y) + (r0.z + r0.w)) + ((r1.x + r1.y) + (r1.z + r1.w));
    }
}

// ---------------------------------------------------------------------------
// Kernel 2: softmax
// ---------------------------------------------------------------------------
__global__ __launch_bounds__(256) void softmax_kernel(float* __restrict__ attn_out) {
    int b = blockIdx.x;
    int tid = threadIdx.x;
    __shared__ float rbuf[256];

    float vals[8];
    float lmax = -1e30f;
#pragma unroll
    for (int i = 0; i < 8; i++) {
        float x = g_scores[b * Ssz + tid + i * 256];
        vals[i] = x;
        lmax = fmaxf(lmax, x);
    }
    rbuf[tid] = lmax;
    __syncthreads();
    for (int off = 128; off; off >>= 1) {
        if (tid < off) rbuf[tid] = fmaxf(rbuf[tid], rbuf[tid + off]);
        __syncthreads();
    }
    float mx = rbuf[0];
    __syncthreads();

    float lsum = 0.f;
#pragma unroll
    for (int i = 0; i < 8; i++) {
        float e = expf(vals[i] - mx);
        vals[i] = e;
        lsum += e;
    }
    rbuf[tid] = lsum;
    __syncthreads();
    for (int off = 128; off; off >>= 1) {
        if (tid < off) rbuf[tid] += rbuf[tid + off];
        __syncthreads();
    }
    float inv = 1.f / rbuf[0];
#pragma unroll
    for (int i = 0; i < 8; i++)
        attn_out[b * Ssz + tid + i * 256] = vals[i] * inv;
}

// ---------------------------------------------------------------------------
// Kernel 3a: context partials from the fp16 enc image (half the DRAM traffic)
// grid (Bsz, CSPLIT), 128 threads; thread t covers cols [4t, 4t+4).
// ---------------------------------------------------------------------------
__global__ __launch_bounds__(128) void context_part_kernel(const float* __restrict__ attn) {
    const int SCHUNK = Ssz / CSPLIT;   // 128
    int b = blockIdx.x;
    int split = blockIdx.y;
    int e4 = threadIdx.x;              // 4-half column group 0..127

    __shared__ float wsm[128];
    wsm[threadIdx.x] = attn[b * Ssz + split * SCHUNK + threadIdx.x];
    __syncthreads();

    const __half* encb = g_ench + ((size_t)b * Ssz + split * SCHUNK) * ENCd;
    float4 acc = make_float4(0.f, 0.f, 0.f, 0.f);
#pragma unroll 8
    for (int s = 0; s < SCHUNK; s++) {
        float w = wsm[s];
        uint2 u = *reinterpret_cast<const uint2*>(encb + (size_t)s * ENCd + e4 * 4);
        float2 x0 = __half22float2(*reinterpret_cast<__half2*>(&u.x));
        float2 x1 = __half22float2(*reinterpret_cast<__half2*>(&u.y));
        acc.x += w * x0.x; acc.y += w * x0.y; acc.z += w * x1.x; acc.w += w * x1.y;
    }
    *reinterpret_cast<float4*>(&g_ctx_part[((size_t)split * Bsz + b) * ENCd + e4 * 4]) = acc;
}

__global__ __launch_bounds__(256) void context_reduce_kernel(float* __restrict__ ctx_out) {
    int i = blockIdx.x * 256 + threadIdx.x;
    float s = 0.f;
#pragma unroll
    for (int p = 0; p < CSPLIT; p++) s += g_ctx_part[(size_t)p * Bsz * ENCd + i];
    ctx_out[i] = s;
}

// ---------------------------------------------------------------------------
extern "C" void kernel_launch(void* const* d_in, const int* in_sizes, int n_in,
                              void* d_out, int out_size) {
    const float* enc       = (const float*)d_in[0];
    const float* dec_state = (const float*)d_in[1];
    const float* W_enc     = (const float*)d_in[2];
    const float* W_dec     = (const float*)d_in[3];
    const float* v         = (const float*)d_in[4];

    float* out  = (float*)d_out;
    float* ctx  = out;
    float* attn = out + Bsz * ENCd;

    cudaFuncSetAttribute(scores_kernel,
                         cudaFuncAttributeMaxDynamicSharedMemorySize, SM_TOTAL);

    prep_bh_kernel<<<(ENCd * ATTNd) / 256, 256>>>(W_enc);
    dec_proj_kernel<<<Bsz, 256>>>(dec_state, W_dec);

    dim3 g1(Ssz / TILE_S, Bsz);
    scores_kernel<<<g1, NTHR, SM_TOTAL>>>(enc, v);

    softmax_kernel<<<Bsz, 256>>>(attn);

    dim3 g3(Bsz, CSPLIT);
    context_part_kernel<<<g3, 128>>>(attn);
    context_reduce_kernel<<<(Bsz * ENCd) / 256, 256>>>(ctx);
}

// round 10
// speedup vs baseline: 1.0176x; 1.0176x over previous
#include <cuda_runtime.h>
#include <cuda_fp16.h>
#include <math.h>
#include <stdint.h>

#define Bsz   64
#define Ssz   2048
#define ENCd  512
#define ATTNd 256

#define TILE_S 128
#define KC     64                    // k per chunk
#define NCHUNK (ENCd / KC)           // 8
#define ABYTES (TILE_S * 128)        // 16384 (128 rows x 128B fp16)
#define BBYTES (ATTNd * 128)         // 32768
#define NTHR   512

// smem offsets
#define SM_DP   0
#define SM_V    1024
#define SM_RED  2048                 // 128*8 floats = 4KB
#define SM_A0   8192
#define SM_B0   (SM_A0 + 2 * ABYTES)          // 40960
#define SM_TOTAL (SM_B0 + 2 * BBYTES)         // 106496

#define CSPLIT 16

__device__ float  g_dec_proj[Bsz * ATTNd];
__device__ float  g_scores[Bsz * Ssz];
__device__ float  g_ctx_part[CSPLIT * Bsz * ENCd];
__device__ __half g_Bh[ENCd * ATTNd];          // pre-swizzled fp16 W_enc^T image
__device__ __half g_ench[(size_t)Bsz * Ssz * ENCd];  // fp16 enc image (written by scores)

// ---------------------------------------------------------------------------
// helpers
// ---------------------------------------------------------------------------
__device__ __forceinline__ float tanh_fast(float x) {
    float y;
    asm("tanh.approx.f32 %0, %1;" : "=f"(y) : "f"(x));
    return y;
}
__device__ __forceinline__ uint32_t smem_u32(const void* p) {
    uint32_t a;
    asm("{ .reg .u64 t; cvta.to.shared.u64 t, %1; cvt.u32.u64 %0, t; }" : "=r"(a) : "l"(p));
    return a;
}
__device__ __forceinline__ uint32_t pack_h2(float lo, float hi) {
    uint32_t r;
    asm("cvt.rn.f16x2.f32 %0, %1, %2;" : "=r"(r) : "f"(hi), "f"(lo));
    return r;
}
__device__ __forceinline__ void cp_async16(uint32_t dst, const void* src) {
    asm volatile("cp.async.cg.shared.global [%0], [%1], 16;" :: "r"(dst), "l"(src));
}
#define CP_COMMIT() asm volatile("cp.async.commit_group;" ::: "memory")

__device__ __forceinline__ void ldsm_x4(uint32_t* r, uint32_t addr) {
    asm volatile("ldmatrix.sync.aligned.m8n8.x4.shared.b16 {%0,%1,%2,%3}, [%4];"
                 : "=r"(r[0]), "=r"(r[1]), "=r"(r[2]), "=r"(r[3]) : "r"(addr));
}
__device__ __forceinline__ void mma_f16(float c[4], const uint32_t a[4],
                                        uint32_t b0, uint32_t b1) {
    asm volatile(
        "mma.sync.aligned.m16n8k16.row.col.f32.f16.f16.f32 "
        "{%0,%1,%2,%3}, {%4,%5,%6,%7}, {%8,%9}, {%0,%1,%2,%3};"
        : "+f"(c[0]), "+f"(c[1]), "+f"(c[2]), "+f"(c[3])
        : "r"(a[0]), "r"(a[1]), "r"(a[2]), "r"(a[3]), "r"(b0), "r"(b1));
}

// ---------------------------------------------------------------------------
// Kernel P: merged prep. Blocks 0..511: build pre-swizzled fp16 W_enc^T image.
// Blocks 512..575: dec_proj for batch b = blockIdx.x - 512.
// ---------------------------------------------------------------------------
__global__ __launch_bounds__(256) void prep_kernel(const float* __restrict__ W_enc,
                                                   const float* __restrict__ dec_state,
                                                   const float* __restrict__ W_dec) {
    if (blockIdx.x < 512) {
        int idx = blockIdx.x * 256 + threadIdx.x;   // k-major
        int k = idx >> 8, n = idx & 255;
        int c = k >> 6, j = (k >> 3) & 7, w = k & 7;
        int phys = j ^ (n & 7);
        g_Bh[(((size_t)c * 256 + n) * 8 + phys) * 8 + w] = __float2half_rn(W_enc[idx]);
    } else {
        int b = blockIdx.x - 512;
        int n = threadIdx.x;
        __shared__ float ds[ENCd];
        for (int i = threadIdx.x; i < ENCd; i += 256) ds[i] = dec_state[b * ENCd + i];
        __syncthreads();
        float a0 = 0.f, a1 = 0.f, a2 = 0.f, a3 = 0.f;
#pragma unroll 4
        for (int d = 0; d < ENCd; d += 4) {
            a0 += ds[d]     * W_dec[(d)     * ATTNd + n];
            a1 += ds[d + 1] * W_dec[(d + 1) * ATTNd + n];
            a2 += ds[d + 2] * W_dec[(d + 2) * ATTNd + n];
            a3 += ds[d + 3] * W_dec[(d + 3) * ATTNd + n];
        }
        g_dec_proj[b * ATTNd + n] = (a0 + a1) + (a2 + a3);
    }
}

// ---------------------------------------------------------------------------
// Kernel 1: scores via fp16 mma.sync (fp32 acc), 512 threads.
// Also writes the converted fp16 A-tiles back to g_ench.
// ---------------------------------------------------------------------------
__global__ __launch_bounds__(NTHR) void scores_kernel(const float* __restrict__ enc,
                                                      const float* __restrict__ v) {
    extern __shared__ __align__(1024) char sm[];
    const uint32_t smb = smem_u32(sm);
    const int tid = threadIdx.x, wid = tid >> 5, lane = tid & 31;
    const int b = blockIdx.y, s0 = blockIdx.x * TILE_S;
    const int gid = lane >> 2, tig = lane & 3;
    const int warp_m = wid >> 3, warp_n = wid & 7;
    const int m_base = warp_m * 64, n_base = warp_n * 32;

    float* dp_sm = (float*)(sm + SM_DP);
    float* v_sm  = (float*)(sm + SM_V);
    float* red   = (float*)(sm + SM_RED);

    if (tid < ATTNd) {
        dp_sm[tid] = g_dec_proj[b * ATTNd + tid];
        v_sm[tid]  = v[tid];
    }

    float acc[4][4][4];
#pragma unroll
    for (int mt = 0; mt < 4; mt++)
#pragma unroll
        for (int nt = 0; nt < 4; nt++)
#pragma unroll
            for (int i = 0; i < 4; i++) acc[mt][nt][i] = 0.f;

    const float* encb = enc + ((size_t)b * Ssz + s0) * ENCd;

    // ldmatrix address invariants
    const int lane15 = lane & 15;
    const int l16 = lane >> 4;                 // A k-half select
    int a_rowrel[4], a_rx[4];
#pragma unroll
    for (int mt = 0; mt < 4; mt++) {
        int r = m_base + mt * 16 + lane15;
        a_rowrel[mt] = r * 128;
        a_rx[mt] = r & 7;
    }
    const int b_lrow = (lane & 7) + ((lane >> 4) & 1) * 8;
    const int b_co = (lane >> 3) & 1;          // B k-half select
    int b_rowrel[2], b_rx[2];
#pragma unroll
    for (int pr = 0; pr < 2; pr++) {
        int r = n_base + pr * 16 + b_lrow;
        b_rowrel[pr] = r * 128;
        b_rx[pr] = r & 7;
    }

    // A staging: thread -> row = tid>>2 (0..127), quarter aq = tid&3 (16 k's)
    const int arow = tid >> 2, aq = tid & 3, arx = arow & 7;
    const float* asrc = encb + (size_t)arow * ENCd + aq * 16;
    char* const abase = sm + SM_A0 + arow * 128;
    __half* const hdst = g_ench + ((size_t)b * Ssz + s0 + arow) * ENCd + aq * 16;

    float4 pa[4];
#define LDG_A(c_) do {                                                         \
        const float* p_ = asrc + (c_) * KC;                                    \
        _Pragma("unroll")                                                      \
        for (int q_ = 0; q_ < 4; q_++)                                         \
            pa[q_] = *reinterpret_cast<const float4*>(p_ + q_ * 4);            \
    } while (0)

#define STS_A(st_, c_) do {                                                    \
        char* ab_ = abase + (st_) * ABYTES;                                    \
        uint4 u0_, u1_;                                                        \
        u0_.x = pack_h2(pa[0].x, pa[0].y);                                     \
        u0_.y = pack_h2(pa[0].z, pa[0].w);                                     \
        u0_.z = pack_h2(pa[1].x, pa[1].y);                                     \
        u0_.w = pack_h2(pa[1].z, pa[1].w);                                     \
        u1_.x = pack_h2(pa[2].x, pa[2].y);                                     \
        u1_.y = pack_h2(pa[2].z, pa[2].w);                                     \
        u1_.z = pack_h2(pa[3].x, pa[3].y);                                     \
        u1_.w = pack_h2(pa[3].z, pa[3].w);                                     \
        *reinterpret_cast<uint4*>(ab_ + (((aq * 2) ^ arx) << 4)) = u0_;        \
        *reinterpret_cast<uint4*>(ab_ + (((aq * 2 + 1) ^ arx) << 4)) = u1_;    \
        uint4* g_ = reinterpret_cast<uint4*>(hdst + (c_) * KC);                \
        g_[0] = u0_;                                                           \
        g_[1] = u1_;                                                           \
    } while (0)

#define CPA_B(c_, st_) do {                                                    \
        uint32_t bd_ = smb + SM_B0 + (st_) * BBYTES;                           \
        const char* bs_ = (const char*)g_Bh + (size_t)(c_) * BBYTES;           \
        _Pragma("unroll")                                                      \
        for (int i_ = 0; i_ < 4; i_++) {                                       \
            int q_ = tid + i_ * NTHR;                                          \
            cp_async16(bd_ + q_ * 16, bs_ + q_ * 16);                          \
        }                                                                      \
        CP_COMMIT();                                                           \
    } while (0)

    // prologue
    LDG_A(0);
    CPA_B(0, 0);

    for (int c = 0; c < NCHUNK; c++) {
        const int st = c & 1;
        STS_A(st, c);
        asm volatile("cp.async.wait_group 0;" ::: "memory");
        __syncthreads();

        if (c + 1 < NCHUNK) {
            CPA_B(c + 1, st ^ 1);
            LDG_A(c + 1);
        }

        const uint32_t Au = smb + SM_A0 + st * ABYTES;
        const uint32_t Bu = smb + SM_B0 + st * BBYTES;
#pragma unroll
        for (int kk = 0; kk < 4; kk++) {
            uint32_t af[4][4], bf[2][4];
#pragma unroll
            for (int mt = 0; mt < 4; mt++)
                ldsm_x4(af[mt], Au + a_rowrel[mt] + (((2 * kk + l16) ^ a_rx[mt]) << 4));
#pragma unroll
            for (int pr = 0; pr < 2; pr++)
                ldsm_x4(bf[pr], Bu + b_rowrel[pr] + (((2 * kk + b_co) ^ b_rx[pr]) << 4));
#pragma unroll
            for (int mt = 0; mt < 4; mt++)
#pragma unroll
                for (int nt = 0; nt < 4; nt++) {
                    int pr = nt >> 1, bi = (nt & 1) * 2;
                    mma_f16(acc[mt][nt], af[mt], bf[pr][bi], bf[pr][bi + 1]);
                }
        }
    }
#undef LDG_A
#undef STS_A
#undef CPA_B

    // Epilogue: rowsum over this warp's n32 of tanh(D + dec_proj) * v
    float rowsum[8];
#pragma unroll
    for (int i = 0; i < 8; i++) rowsum[i] = 0.f;
#pragma unroll
    for (int mt = 0; mt < 4; mt++)
#pragma unroll
        for (int nt = 0; nt < 4; nt++) {
            int c0 = n_base + nt * 8 + tig * 2;
#pragma unroll
            for (int i = 0; i < 2; i++)
#pragma unroll
                for (int j = 0; j < 2; j++) {
                    int col = c0 + j;
                    rowsum[mt * 2 + i] +=
                        tanh_fast(acc[mt][nt][i * 2 + j] + dp_sm[col]) * v_sm[col];
                }
        }
#pragma unroll
    for (int i = 0; i < 8; i++) {
        rowsum[i] += __shfl_xor_sync(0xffffffff, rowsum[i], 1);
        rowsum[i] += __shfl_xor_sync(0xffffffff, rowsum[i], 2);
    }
    __syncthreads();
    if (tig == 0) {
#pragma unroll
        for (int mt = 0; mt < 4; mt++)
#pragma unroll
            for (int i = 0; i < 2; i++) {
                int row = m_base + mt * 16 + gid + 8 * i;
                red[row * 8 + warp_n] = rowsum[mt * 2 + i];
            }
    }
    __syncthreads();
    if (tid < TILE_S) {
        float4 r0 = *reinterpret_cast<float4*>(&red[tid * 8]);
        float4 r1 = *reinterpret_cast<float4*>(&red[tid * 8 + 4]);
        g_scores[b * Ssz + s0 + tid] =
            ((r0.x + r0.y) + (r0.z + r0.w)) + ((r1.x + r1.y) + (r1.z + r1.w));
    }
}

// ---------------------------------------------------------------------------
// Kernel 2: fused softmax + context partials.
// grid (Bsz, CSPLIT), 128 threads. Each CTA recomputes the (deterministic)
// per-batch softmax stats from g_scores, writes its 128-wide attn slice,
// then accumulates its S-chunk's weighted sum of the fp16 enc image.
// ---------------------------------------------------------------------------
__global__ __launch_bounds__(128) void context_part_kernel(float* __restrict__ attn_out) {
    const int SCHUNK = Ssz / CSPLIT;   // 128
    int b = blockIdx.x;
    int split = blockIdx.y;
    int tid = threadIdx.x;

    __shared__ float rbuf[128];
    __shared__ float wsm[128];

    // --- softmax stats over the full row (identical order in every CTA of b) ---
    const float* srow = g_scores + b * Ssz;
    float lmax = -1e30f;
#pragma unroll
    for (int i = 0; i < 16; i++) lmax = fmaxf(lmax, srow[tid + i * 128]);
    rbuf[tid] = lmax;
    __syncthreads();
    for (int off = 64; off; off >>= 1) {
        if (tid < off) rbuf[tid] = fmaxf(rbuf[tid], rbuf[tid + off]);
        __syncthreads();
    }
    float mx = rbuf[0];
    __syncthreads();
    float lsum = 0.f;
#pragma unroll
    for (int i = 0; i < 16; i++) lsum += expf(srow[tid + i * 128] - mx);
    rbuf[tid] = lsum;
    __syncthreads();
    for (int off = 64; off; off >>= 1) {
        if (tid < off) rbuf[tid] += rbuf[tid + off];
        __syncthreads();
    }
    float inv = 1.f / rbuf[0];

    // --- this CTA's 128 weights: write attn slice + stash in smem ---
    float w = expf(srow[split * SCHUNK + tid] - mx) * inv;
    wsm[tid] = w;
    attn_out[b * Ssz + split * SCHUNK + tid] = w;
    __syncthreads();

    // --- weighted sum over this S-chunk (fp16 enc image) ---
    const __half* encb = g_ench + ((size_t)b * Ssz + split * SCHUNK) * ENCd;
    float4 acc = make_float4(0.f, 0.f, 0.f, 0.f);
#pragma unroll 8
    for (int s = 0; s < SCHUNK; s++) {
        float ws = wsm[s];
        uint2 u = *reinterpret_cast<const uint2*>(encb + (size_t)s * ENCd + tid * 4);
        float2 x0 = __half22float2(*reinterpret_cast<__half2*>(&u.x));
        float2 x1 = __half22float2(*reinterpret_cast<__half2*>(&u.y));
        acc.x += ws * x0.x; acc.y += ws * x0.y; acc.z += ws * x1.x; acc.w += ws * x1.y;
    }
    *reinterpret_cast<float4*>(&g_ctx_part[((size_t)split * Bsz + b) * ENCd + tid * 4]) = acc;
}

__global__ __launch_bounds__(256) void context_reduce_kernel(float* __restrict__ ctx_out) {
    int i = blockIdx.x * 256 + threadIdx.x;
    float s = 0.f;
#pragma unroll
    for (int p = 0; p < CSPLIT; p++) s += g_ctx_part[(size_t)p * Bsz * ENCd + i];
    ctx_out[i] = s;
}

// ---------------------------------------------------------------------------
extern "C" void kernel_launch(void* const* d_in, const int* in_sizes, int n_in,
                              void* d_out, int out_size) {
    const float* enc       = (const float*)d_in[0];
    const float* dec_state = (const float*)d_in[1];
    const float* W_enc     = (const float*)d_in[2];
    const float* W_dec     = (const float*)d_in[3];
    const float* v         = (const float*)d_in[4];

    float* out  = (float*)d_out;
    float* ctx  = out;
    float* attn = out + Bsz * ENCd;

    cudaFuncSetAttribute(scores_kernel,
                         cudaFuncAttributeMaxDynamicSharedMemorySize, SM_TOTAL);

    prep_kernel<<<512 + Bsz, 256>>>(W_enc, dec_state, W_dec);

    dim3 g1(Ssz / TILE_S, Bsz);
    scores_kernel<<<g1, NTHR, SM_TOTAL>>>(enc, v);

    dim3 g3(Bsz, CSPLIT);
    context_part_kernel<<<g3, 128>>>(attn);
    context_reduce_kernel<<<(Bsz * ENCd) / 256, 256>>>(ctx);
}